// round 13
// baseline (speedup 1.0000x reference)
#include <cuda_runtime.h>
#include <cuda_fp16.h>
#include <cstdint>
#include <math.h>

#define B_ 64
#define S_ 2048
#define H_ 1024
#define M_ (B_*S_)
#define NTILES 8          // H_/128 N-blocks
#define KT 64             // k elems per tile
#define K_ITERS (H_/KT)   // 16
#define RS 144            // smem row stride bytes (128B data + 16 pad)
#define MT 256            // CTA tile M
#define NT 128            // CTA tile N
#define ASTG (MT*RS)      // 36864
#define BSTG (NT*RS)      // 18432
#define STG  (ASTG+BSTG)  // 55296
#define NSTG 3
#define DYN_BYTES (NSTG*STG)   // 165888

__device__ float  g_dp[B_ * H_];
__device__ float  g_part[NTILES * M_];
__device__ __half g_ench[(size_t)M_ * H_];   // 256 MB fp16 copy of enc
__device__ __half g_wh[(size_t)H_ * H_];     // 2 MB fp16 copy of W_enc

__device__ __forceinline__ uint32_t smem_u32(const void* p) {
    uint32_t a;
    asm("{ .reg .u64 t; cvta.to.shared.u64 t, %1; cvt.u32.u64 %0, t; }" : "=r"(a) : "l"(p));
    return a;
}
__device__ __forceinline__ void cp_async16(uint32_t dst, const void* src) {
    asm volatile("cp.async.cg.shared.global [%0], [%1], 16;" :: "r"(dst), "l"(src));
}
__device__ __forceinline__ void ldsm_x4(uint32_t r[4], uint32_t addr) {
    asm volatile("ldmatrix.sync.aligned.m8n8.x4.shared.b16 {%0,%1,%2,%3}, [%4];"
                 : "=r"(r[0]), "=r"(r[1]), "=r"(r[2]), "=r"(r[3]) : "r"(addr));
}
// fp16-accumulate HMMA: D,C are 2 packed f16x2 regs.
__device__ __forceinline__ void mma_f16acc(uint32_t d[2], const uint32_t a[4],
                                           uint32_t b0, uint32_t b1) {
    asm volatile(
        "mma.sync.aligned.m16n8k16.row.col.f16.f16.f16.f16 "
        "{%0,%1}, {%2,%3,%4,%5}, {%6,%7}, {%0,%1};"
        : "+r"(d[0]), "+r"(d[1])
        : "r"(a[0]), "r"(a[1]), "r"(a[2]), "r"(a[3]), "r"(b0), "r"(b1));
}
__device__ __forceinline__ float fast_tanh(float x) {
    float y; asm("tanh.approx.f32 %0, %1;" : "=f"(y) : "f"(x)); return y;
}

// ---------------------------------------------------------------------------
__global__ void cvt_enc_kernel(const float* __restrict__ src) {
    size_t c = (size_t)blockIdx.x * blockDim.x + threadIdx.x;
    const float4* s = (const float4*)src + c * 2;
    float4 a = s[0], b = s[1];
    __half2 h[4];
    h[0] = __floats2half2_rn(a.x, a.y);
    h[1] = __floats2half2_rn(a.z, a.w);
    h[2] = __floats2half2_rn(b.x, b.y);
    h[3] = __floats2half2_rn(b.z, b.w);
    *((uint4*)g_ench + c) = *(uint4*)h;
}
__global__ void cvt_w_kernel(const float* __restrict__ src) {
    size_t c = (size_t)blockIdx.x * blockDim.x + threadIdx.x;
    const float4* s = (const float4*)src + c * 2;
    float4 a = s[0], b = s[1];
    __half2 h[4];
    h[0] = __floats2half2_rn(a.x, a.y);
    h[1] = __floats2half2_rn(a.z, a.w);
    h[2] = __floats2half2_rn(b.x, b.y);
    h[3] = __floats2half2_rn(b.z, b.w);
    *((uint4*)g_wh + c) = *(uint4*)h;
}

// ---------------------------------------------------------------------------
__global__ void dec_proj_kernel(const float* __restrict__ dec,
                                const float* __restrict__ Wdec) {
    int wid  = (blockIdx.x * blockDim.x + threadIdx.x) >> 5;
    int lane = threadIdx.x & 31;
    int o  = wid >> 4;
    int b0 = (wid & 15) * 4;
    const float* wr = Wdec + (size_t)o * H_;
    const float* d0 = dec + (size_t)(b0 + 0) * H_;
    const float* d1 = dec + (size_t)(b0 + 1) * H_;
    const float* d2 = dec + (size_t)(b0 + 2) * H_;
    const float* d3 = dec + (size_t)(b0 + 3) * H_;
    float a0 = 0.f, a1 = 0.f, a2 = 0.f, a3 = 0.f;
    #pragma unroll 4
    for (int h = lane; h < H_; h += 32) {
        float w = wr[h];
        a0 = fmaf(w, d0[h], a0);
        a1 = fmaf(w, d1[h], a1);
        a2 = fmaf(w, d2[h], a2);
        a3 = fmaf(w, d3[h], a3);
    }
    #pragma unroll
    for (int off = 16; off; off >>= 1) {
        a0 += __shfl_down_sync(0xffffffffu, a0, off);
        a1 += __shfl_down_sync(0xffffffffu, a1, off);
        a2 += __shfl_down_sync(0xffffffffu, a2, off);
        a3 += __shfl_down_sync(0xffffffffu, a3, off);
    }
    if (lane == 0) {
        g_dp[(size_t)(b0 + 0) * H_ + o] = a0;
        g_dp[(size_t)(b0 + 1) * H_ + o] = a1;
        g_dp[(size_t)(b0 + 2) * H_ + o] = a2;
        g_dp[(size_t)(b0 + 3) * H_ + o] = a3;
    }
}

// ---------------------------------------------------------------------------
// Fused fp16 MMA GEMM (encH @ WencH^T), f16 accumulators promoted to an fp32
// shadow every 4 k-tiles (K-chunk 256), + tanh(.+dec_proj).v partial reduce.
// CTA tile 256(M)x128(N), k-tile 64; 8 warps = 4(M)x2(N), warp tile 64x64;
// cp.async 3-stage ring (166 KB dynamic smem).
// ---------------------------------------------------------------------------
__global__ void __launch_bounds__(256, 1)
fused_score_kernel(const float* __restrict__ v) {
    extern __shared__ __align__(16) char dynsm[];
    __shared__ float dp_sh[NT];
    __shared__ float v_sh[NT];
    __shared__ float part_sh[2][MT];

    const int tid   = threadIdx.x;
    const int lane  = tid & 31;
    const int warp  = tid >> 5;
    const int warpM = warp & 3;     // 0..3
    const int warpN = warp >> 2;    // 0..1
    const int g = lane >> 2;
    const int t = lane & 3;

    const int nBase = blockIdx.x * NT;
    const int mBase = blockIdx.y * MT;
    const int b     = mBase >> 11;  // 256 | 2048 -> single batch per tile

    if (tid < NT) {
        dp_sh[tid] = g_dp[(size_t)b * H_ + nBase + tid];
        v_sh[tid]  = v[nBase + tid];
    }

    const uint32_t sm0 = smem_u32(dynsm);
    const __half* encH = g_ench;
    const __half* wH   = g_wh;

    float    accf[4][8][4];   // fp32 shadow
    uint32_t hacc[4][8][2];   // f16x2 running accumulators
    #pragma unroll
    for (int mi = 0; mi < 4; mi++)
        #pragma unroll
        for (int ni = 0; ni < 8; ni++) {
            #pragma unroll
            for (int c = 0; c < 4; c++) accf[mi][ni][c] = 0.f;
            hacc[mi][ni][0] = 0u; hacc[mi][ni][1] = 0u;
        }

    // cp.async per ktile(64): A = 2048 chunks (16B), B = 1024; 256 threads.
#define ISSUE(J) {                                                          \
    const uint32_t sa_ = sm0 + ((J) % NSTG) * STG;                          \
    const uint32_t sb_ = sa_ + ASTG;                                        \
    const size_t ko_ = (size_t)(J) * KT;                                    \
    _Pragma("unroll")                                                       \
    for (int i_ = 0; i_ < 8; i_++) {                                        \
        int c_ = tid + (i_ << 8);                                           \
        int r_ = c_ >> 3, q_ = c_ & 7;                                      \
        cp_async16(sa_ + r_ * RS + q_ * 16,                                 \
                   encH + (size_t)(mBase + r_) * H_ + ko_ + q_ * 8);        \
    }                                                                       \
    _Pragma("unroll")                                                       \
    for (int i_ = 0; i_ < 4; i_++) {                                        \
        int c_ = tid + (i_ << 8);                                           \
        int r_ = c_ >> 3, q_ = c_ & 7;                                      \
        cp_async16(sb_ + r_ * RS + q_ * 16,                                 \
                   wH + (size_t)(nBase + r_) * H_ + ko_ + q_ * 8);          \
    } }

    // ldmatrix per-lane address components
    const int aRow = warpM * 64 + (lane & 7) + ((lane >> 3) & 1) * 8;
    const int aCol = ((lane >> 4) & 1) * 16;
    const int bRow = warpN * 64 + (lane >> 4) * 8 + (lane & 7);
    const int bCol = ((lane >> 3) & 1) * 16;

#define COMPUTE(BUF) {                                                     \
    const uint32_t Ab = sm0 + (BUF) * STG;                                  \
    const uint32_t Bb = Ab + ASTG;                                          \
    _Pragma("unroll")                                                       \
    for (int ks = 0; ks < 4; ks++) {                                        \
        uint32_t af[4][4], bf[4][4];                                        \
        _Pragma("unroll")                                                   \
        for (int mi = 0; mi < 4; mi++)                                      \
            ldsm_x4(af[mi], Ab + (aRow + mi * 16) * RS + ks * 32 + aCol);   \
        _Pragma("unroll")                                                   \
        for (int nj = 0; nj < 4; nj++)                                      \
            ldsm_x4(bf[nj], Bb + (bRow + nj * 16) * RS + ks * 32 + bCol);   \
        _Pragma("unroll")                                                   \
        for (int mi = 0; mi < 4; mi++) {                                    \
            _Pragma("unroll")                                               \
            for (int nj = 0; nj < 4; nj++) {                                \
                mma_f16acc(hacc[mi][2*nj],   af[mi], bf[nj][0], bf[nj][1]); \
                mma_f16acc(hacc[mi][2*nj+1], af[mi], bf[nj][2], bf[nj][3]); \
            }                                                               \
        }                                                                   \
    } }

    // promote f16 accumulators into the fp32 shadow, reset them
#define PROMOTE() {                                                        \
    _Pragma("unroll")                                                       \
    for (int mi = 0; mi < 4; mi++) {                                        \
        _Pragma("unroll")                                                   \
        for (int ni = 0; ni < 8; ni++) {                                    \
            float2 f0 = __half22float2(*(__half2*)&hacc[mi][ni][0]);        \
            float2 f1 = __half22float2(*(__half2*)&hacc[mi][ni][1]);        \
            accf[mi][ni][0] += f0.x;  accf[mi][ni][1] += f0.y;              \
            accf[mi][ni][2] += f1.x;  accf[mi][ni][3] += f1.y;              \
            hacc[mi][ni][0] = 0u;     hacc[mi][ni][1] = 0u;                 \
        }                                                                   \
    } }

    // prologue: 2 stages in flight
    ISSUE(0); asm volatile("cp.async.commit_group;");
    ISSUE(1); asm volatile("cp.async.commit_group;");

    #pragma unroll 1
    for (int kt = 0; kt < K_ITERS; kt++) {
        asm volatile("cp.async.wait_group 1;");
        __syncthreads();
        COMPUTE(kt % NSTG);
        if ((kt & 3) == 3) PROMOTE();    // K-chunk = 256
        if (kt + 2 < K_ITERS) ISSUE(kt + 2);
        asm volatile("cp.async.commit_group;");
    }
#undef ISSUE
#undef COMPUTE
#undef PROMOTE

    // Epilogue: energy = tanh(accf + dec_proj), partial = sum_col energy * v
    float rs[8];
    #pragma unroll
    for (int i = 0; i < 8; i++) rs[i] = 0.f;

    #pragma unroll
    for (int mi = 0; mi < 4; mi++) {
        #pragma unroll
        for (int ni = 0; ni < 8; ni++) {
            int c0 = warpN * 64 + ni * 8 + 2 * t;
            float d0 = dp_sh[c0],     d1 = dp_sh[c0 + 1];
            float w0 = v_sh[c0],      w1 = v_sh[c0 + 1];
            rs[2 * mi]     += fast_tanh(accf[mi][ni][0] + d0) * w0
                            + fast_tanh(accf[mi][ni][1] + d1) * w1;
            rs[2 * mi + 1] += fast_tanh(accf[mi][ni][2] + d0) * w0
                            + fast_tanh(accf[mi][ni][3] + d1) * w1;
        }
    }
    #pragma unroll
    for (int i = 0; i < 8; i++) {
        rs[i] += __shfl_xor_sync(0xffffffffu, rs[i], 1);
        rs[i] += __shfl_xor_sync(0xffffffffu, rs[i], 2);
    }
    if (t == 0) {
        #pragma unroll
        for (int mi = 0; mi < 4; mi++) {
            part_sh[warpN][warpM * 64 + mi * 16 + g]     = rs[2 * mi];
            part_sh[warpN][warpM * 64 + mi * 16 + g + 8] = rs[2 * mi + 1];
        }
    }
    __syncthreads();
    {
        float sres = part_sh[0][tid] + part_sh[1][tid];
        g_part[(size_t)blockIdx.x * M_ + mBase + tid] = sres;
    }
}

// ---------------------------------------------------------------------------
// Softmax; mask dtype sniffed inline from word 0 (uint8 / int32 / float32).
// ---------------------------------------------------------------------------
__global__ void softmax_kernel(const void* __restrict__ mask,
                               float* __restrict__ attn) {
    const int b   = blockIdx.x;
    const int tid = threadIdx.x;  // 256
    __shared__ float red[8];

    unsigned w0 = ((const unsigned int*)mask)[0];
    const int mode = (w0 == 0x01010101u) ? 0 : (w0 == 0x3F800000u) ? 2 : 1;

    float vals[8];
    float lmax = -1e30f;
    #pragma unroll
    for (int i = 0; i < 8; i++) {
        size_t f = (size_t)b * S_ + tid + i * 256;
        float sc = 0.f;
        #pragma unroll
        for (int x = 0; x < NTILES; x++) sc += g_part[(size_t)x * M_ + f];
        bool alive;
        if (mode == 0)      alive = ((const unsigned char*)mask)[f] != 0;
        else if (mode == 1) alive = ((const int*)mask)[f] != 0;
        else                alive = ((const float*)mask)[f] != 0.0f;
        if (!alive) sc = -1e9f;
        vals[i] = sc;
        lmax = fmaxf(lmax, sc);
    }
    float m = lmax;
    #pragma unroll
    for (int off = 16; off; off >>= 1)
        m = fmaxf(m, __shfl_xor_sync(0xffffffffu, m, off));
    if ((tid & 31) == 0) red[tid >> 5] = m;
    __syncthreads();
    float bm = red[0];
    #pragma unroll
    for (int i = 1; i < 8; i++) bm = fmaxf(bm, red[i]);

    float lsum = 0.f;
    #pragma unroll
    for (int i = 0; i < 8; i++) {
        vals[i] = expf(vals[i] - bm);
        lsum += vals[i];
    }
    #pragma unroll
    for (int off = 16; off; off >>= 1)
        lsum += __shfl_xor_sync(0xffffffffu, lsum, off);
    __syncthreads();
    if ((tid & 31) == 0) red[tid >> 5] = lsum;
    __syncthreads();
    float tot = 0.f;
    #pragma unroll
    for (int i = 0; i < 8; i++) tot += red[i];
    float inv = 1.f / tot;

    #pragma unroll
    for (int i = 0; i < 8; i++)
        attn[(size_t)b * S_ + tid + i * 256] = vals[i] * inv;
}

// ---------------------------------------------------------------------------
// context from fp16 enc copy (halved read traffic).
// ---------------------------------------------------------------------------
__global__ void context_kernel(const float* __restrict__ attn,
                               float* __restrict__ ctx) {
    const int b  = blockIdx.x;
    const int h  = blockIdx.y * 128 + (threadIdx.x & 127);
    const int sp = threadIdx.x >> 7;
    const __half* e = g_ench + (size_t)b * S_ * H_ + h;
    const float* w = attn + (size_t)b * S_;
    float acc = 0.f;
    #pragma unroll 8
    for (int s = sp; s < S_; s += 2)
        acc = fmaf(w[s], __half2float(e[(size_t)s * H_]), acc);
    __shared__ float sh[256];
    sh[threadIdx.x] = acc;
    __syncthreads();
    if (threadIdx.x < 128)
        ctx[(size_t)b * H_ + h] = sh[threadIdx.x] + sh[threadIdx.x + 128];
}

// ---------------------------------------------------------------------------
extern "C" void kernel_launch(void* const* d_in, const int* in_sizes, int n_in,
                              void* d_out, int out_size) {
    (void)in_sizes; (void)n_in; (void)out_size;
    const float* dec  = (const float*)d_in[0];
    const float* enc  = (const float*)d_in[1];
    const void*  mask = (const void*)d_in[2];
    const float* Wenc = (const float*)d_in[3];
    const float* Wdec = (const float*)d_in[4];
    const float* v    = (const float*)d_in[5];
    float* out  = (float*)d_out;
    float* attn = out + (size_t)B_ * H_;

    cudaFuncSetAttribute(fused_score_kernel,
                         cudaFuncAttributeMaxDynamicSharedMemorySize, DYN_BYTES);

    cvt_enc_kernel<<<65536, 256>>>(enc);
    cvt_w_kernel<<<512, 256>>>(Wenc);
    dec_proj_kernel<<<2048, 256>>>(dec, Wdec);
    dim3 g2(NTILES, M_ / MT);                 // (8, 512), x fastest -> L2 reuse
    fused_score_kernel<<<g2, 256, DYN_BYTES>>>(v);
    softmax_kernel<<<B_, 256>>>(mask, attn);
    context_kernel<<<dim3(B_, H_ / 128), 256>>>(attn, out);
}

// round 14
// speedup vs baseline: 1.0551x; 1.0551x over previous
#include <cuda_runtime.h>
#include <cuda_fp16.h>
#include <cstdint>
#include <math.h>

#define B_ 64
#define S_ 2048
#define H_ 1024
#define M_ (B_*S_)
#define NTILES 8          // H_/128 N-blocks
#define KT 64             // k elems per tile
#define K_ITERS (H_/KT)   // 16
#define RS 144            // smem row stride bytes (128B data + 16 pad)
#define MT 256            // CTA tile M
#define NT 128            // CTA tile N
#define ASTG (MT*RS)      // 36864
#define BSTG (NT*RS)      // 18432
#define STG  (ASTG+BSTG)  // 55296
#define NSTG 3
#define DYN_BYTES (NSTG*STG)   // 165888

__device__ float  g_dp[B_ * H_];
__device__ float  g_part[NTILES * M_];
__device__ __half g_ench[(size_t)M_ * H_];   // 256 MB fp16 copy of enc
__device__ __half g_wh[(size_t)H_ * H_];     // 2 MB fp16 copy of W_enc

__device__ __forceinline__ uint32_t smem_u32(const void* p) {
    uint32_t a;
    asm("{ .reg .u64 t; cvta.to.shared.u64 t, %1; cvt.u32.u64 %0, t; }" : "=r"(a) : "l"(p));
    return a;
}
__device__ __forceinline__ void cp_async16(uint32_t dst, const void* src) {
    asm volatile("cp.async.cg.shared.global [%0], [%1], 16;" :: "r"(dst), "l"(src));
}
__device__ __forceinline__ void ldsm_x4(uint32_t r[4], uint32_t addr) {
    asm volatile("ldmatrix.sync.aligned.m8n8.x4.shared.b16 {%0,%1,%2,%3}, [%4];"
                 : "=r"(r[0]), "=r"(r[1]), "=r"(r[2]), "=r"(r[3]) : "r"(addr));
}
__device__ __forceinline__ void mma_f16(float c[4], const uint32_t a[4],
                                        uint32_t b0, uint32_t b1) {
    asm volatile(
        "mma.sync.aligned.m16n8k16.row.col.f32.f16.f16.f32 "
        "{%0,%1,%2,%3}, {%4,%5,%6,%7}, {%8,%9}, {%0,%1,%2,%3};"
        : "+f"(c[0]), "+f"(c[1]), "+f"(c[2]), "+f"(c[3])
        : "r"(a[0]), "r"(a[1]), "r"(a[2]), "r"(a[3]), "r"(b0), "r"(b1));
}
__device__ __forceinline__ float fast_tanh(float x) {
    float y; asm("tanh.approx.f32 %0, %1;" : "=f"(y) : "f"(x)); return y;
}

// ---------------------------------------------------------------------------
__global__ void cvt_enc_kernel(const float* __restrict__ src) {
    size_t c = (size_t)blockIdx.x * blockDim.x + threadIdx.x;
    const float4* s = (const float4*)src + c * 2;
    float4 a = s[0], b = s[1];
    __half2 h[4];
    h[0] = __floats2half2_rn(a.x, a.y);
    h[1] = __floats2half2_rn(a.z, a.w);
    h[2] = __floats2half2_rn(b.x, b.y);
    h[3] = __floats2half2_rn(b.z, b.w);
    *((uint4*)g_ench + c) = *(uint4*)h;
}
__global__ void cvt_w_kernel(const float* __restrict__ src) {
    size_t c = (size_t)blockIdx.x * blockDim.x + threadIdx.x;
    const float4* s = (const float4*)src + c * 2;
    float4 a = s[0], b = s[1];
    __half2 h[4];
    h[0] = __floats2half2_rn(a.x, a.y);
    h[1] = __floats2half2_rn(a.z, a.w);
    h[2] = __floats2half2_rn(b.x, b.y);
    h[3] = __floats2half2_rn(b.z, b.w);
    *((uint4*)g_wh + c) = *(uint4*)h;
}

// ---------------------------------------------------------------------------
__global__ void dec_proj_kernel(const float* __restrict__ dec,
                                const float* __restrict__ Wdec) {
    int wid  = (blockIdx.x * blockDim.x + threadIdx.x) >> 5;
    int lane = threadIdx.x & 31;
    int o  = wid >> 4;
    int b0 = (wid & 15) * 4;
    const float* wr = Wdec + (size_t)o * H_;
    const float* d0 = dec + (size_t)(b0 + 0) * H_;
    const float* d1 = dec + (size_t)(b0 + 1) * H_;
    const float* d2 = dec + (size_t)(b0 + 2) * H_;
    const float* d3 = dec + (size_t)(b0 + 3) * H_;
    float a0 = 0.f, a1 = 0.f, a2 = 0.f, a3 = 0.f;
    #pragma unroll 4
    for (int h = lane; h < H_; h += 32) {
        float w = wr[h];
        a0 = fmaf(w, d0[h], a0);
        a1 = fmaf(w, d1[h], a1);
        a2 = fmaf(w, d2[h], a2);
        a3 = fmaf(w, d3[h], a3);
    }
    #pragma unroll
    for (int off = 16; off; off >>= 1) {
        a0 += __shfl_down_sync(0xffffffffu, a0, off);
        a1 += __shfl_down_sync(0xffffffffu, a1, off);
        a2 += __shfl_down_sync(0xffffffffu, a2, off);
        a3 += __shfl_down_sync(0xffffffffu, a3, off);
    }
    if (lane == 0) {
        g_dp[(size_t)(b0 + 0) * H_ + o] = a0;
        g_dp[(size_t)(b0 + 1) * H_ + o] = a1;
        g_dp[(size_t)(b0 + 2) * H_ + o] = a2;
        g_dp[(size_t)(b0 + 3) * H_ + o] = a3;
    }
}

// ---------------------------------------------------------------------------
// Fused fp16 MMA GEMM (encH @ WencH^T) + tanh(.+dec_proj).v partial reduction.
// CTA tile 256(M)x128(N), k-tile 64; 8 warps = 4(M)x2(N), warp tile 64x64;
// cp.async 3-stage ring; f32 accumulators; REGISTER-LEVEL fragment double
// buffering: frags for ks+1 issue before the mma batch of ks.
// ---------------------------------------------------------------------------
__global__ void __launch_bounds__(256, 1)
fused_score_kernel(const float* __restrict__ v) {
    extern __shared__ __align__(16) char dynsm[];
    __shared__ float dp_sh[NT];
    __shared__ float v_sh[NT];
    __shared__ float part_sh[2][MT];

    const int tid   = threadIdx.x;
    const int lane  = tid & 31;
    const int warp  = tid >> 5;
    const int warpM = warp & 3;     // 0..3
    const int warpN = warp >> 2;    // 0..1
    const int g = lane >> 2;
    const int t = lane & 3;

    const int nBase = blockIdx.x * NT;
    const int mBase = blockIdx.y * MT;
    const int b     = mBase >> 11;  // 256 | 2048 -> single batch per tile

    if (tid < NT) {
        dp_sh[tid] = g_dp[(size_t)b * H_ + nBase + tid];
        v_sh[tid]  = v[nBase + tid];
    }

    const uint32_t sm0 = smem_u32(dynsm);
    const __half* encH = g_ench;
    const __half* wH   = g_wh;

    float acc[4][8][4];
    #pragma unroll
    for (int mi = 0; mi < 4; mi++)
        #pragma unroll
        for (int ni = 0; ni < 8; ni++)
            #pragma unroll
            for (int c = 0; c < 4; c++) acc[mi][ni][c] = 0.f;

    // cp.async per ktile(64): A = 2048 chunks (16B), B = 1024; 256 threads.
#define ISSUE(J) {                                                          \
    const uint32_t sa_ = sm0 + ((J) % NSTG) * STG;                          \
    const uint32_t sb_ = sa_ + ASTG;                                        \
    const size_t ko_ = (size_t)(J) * KT;                                    \
    _Pragma("unroll")                                                       \
    for (int i_ = 0; i_ < 8; i_++) {                                        \
        int c_ = tid + (i_ << 8);                                           \
        int r_ = c_ >> 3, q_ = c_ & 7;                                      \
        cp_async16(sa_ + r_ * RS + q_ * 16,                                 \
                   encH + (size_t)(mBase + r_) * H_ + ko_ + q_ * 8);        \
    }                                                                       \
    _Pragma("unroll")                                                       \
    for (int i_ = 0; i_ < 4; i_++) {                                        \
        int c_ = tid + (i_ << 8);                                           \
        int r_ = c_ >> 3, q_ = c_ & 7;                                      \
        cp_async16(sb_ + r_ * RS + q_ * 16,                                 \
                   wH + (size_t)(nBase + r_) * H_ + ko_ + q_ * 8);          \
    } }

    // ldmatrix per-lane address components
    const int aRow = warpM * 64 + (lane & 7) + ((lane >> 3) & 1) * 8;
    const int aCol = ((lane >> 4) & 1) * 16;
    const int bRow = warpN * 64 + (lane >> 4) * 8 + (lane & 7);
    const int bCol = ((lane >> 3) & 1) * 16;

    // frag double buffers (register-level software pipeline over ks)
    uint32_t af[2][4][4], bf[2][4][4];

#define LDFRAG(BUFR, Ab, Bb, KS) {                                          \
    _Pragma("unroll")                                                       \
    for (int mi = 0; mi < 4; mi++)                                          \
        ldsm_x4(af[BUFR][mi], (Ab) + (aRow + mi * 16) * RS + (KS) * 32 + aCol); \
    _Pragma("unroll")                                                       \
    for (int nj = 0; nj < 4; nj++)                                          \
        ldsm_x4(bf[BUFR][nj], (Bb) + (bRow + nj * 16) * RS + (KS) * 32 + bCol); \
    }

#define MMABATCH(BUFR) {                                                    \
    _Pragma("unroll")                                                       \
    for (int mi = 0; mi < 4; mi++) {                                        \
        _Pragma("unroll")                                                   \
        for (int nj = 0; nj < 4; nj++) {                                    \
            mma_f16(acc[mi][2*nj],   af[BUFR][mi], bf[BUFR][nj][0], bf[BUFR][nj][1]); \
            mma_f16(acc[mi][2*nj+1], af[BUFR][mi], bf[BUFR][nj][2], bf[BUFR][nj][3]); \
        }                                                                   \
    } }

#define COMPUTE(BUF) {                                                     \
    const uint32_t Ab = sm0 + (BUF) * STG;                                  \
    const uint32_t Bb = Ab + ASTG;                                          \
    LDFRAG(0, Ab, Bb, 0);                                                   \
    _Pragma("unroll")                                                       \
    for (int ks = 0; ks < 4; ks++) {                                        \
        if (ks < 3) { LDFRAG(((ks + 1) & 1), Ab, Bb, ks + 1); }             \
        MMABATCH((ks & 1));                                                 \
    } }

    // prologue: 2 stages in flight
    ISSUE(0); asm volatile("cp.async.commit_group;");
    ISSUE(1); asm volatile("cp.async.commit_group;");

    #pragma unroll 1
    for (int kt = 0; kt < K_ITERS; kt++) {
        asm volatile("cp.async.wait_group 1;");
        __syncthreads();
        COMPUTE(kt % NSTG);
        if (kt + 2 < K_ITERS) ISSUE(kt + 2);
        asm volatile("cp.async.commit_group;");
    }
#undef ISSUE
#undef COMPUTE
#undef LDFRAG
#undef MMABATCH

    // Epilogue: energy = tanh(acc + dec_proj), partial = sum_col energy * v
    float rs[8];
    #pragma unroll
    for (int i = 0; i < 8; i++) rs[i] = 0.f;

    #pragma unroll
    for (int mi = 0; mi < 4; mi++) {
        #pragma unroll
        for (int ni = 0; ni < 8; ni++) {
            int c0 = warpN * 64 + ni * 8 + 2 * t;
            float d0 = dp_sh[c0],     d1 = dp_sh[c0 + 1];
            float w0 = v_sh[c0],      w1 = v_sh[c0 + 1];
            rs[2 * mi]     += fast_tanh(acc[mi][ni][0] + d0) * w0
                            + fast_tanh(acc[mi][ni][1] + d1) * w1;
            rs[2 * mi + 1] += fast_tanh(acc[mi][ni][2] + d0) * w0
                            + fast_tanh(acc[mi][ni][3] + d1) * w1;
        }
    }
    #pragma unroll
    for (int i = 0; i < 8; i++) {
        rs[i] += __shfl_xor_sync(0xffffffffu, rs[i], 1);
        rs[i] += __shfl_xor_sync(0xffffffffu, rs[i], 2);
    }
    if (t == 0) {
        #pragma unroll
        for (int mi = 0; mi < 4; mi++) {
            part_sh[warpN][warpM * 64 + mi * 16 + g]     = rs[2 * mi];
            part_sh[warpN][warpM * 64 + mi * 16 + g + 8] = rs[2 * mi + 1];
        }
    }
    __syncthreads();
    {
        float sres = part_sh[0][tid] + part_sh[1][tid];
        g_part[(size_t)blockIdx.x * M_ + mBase + tid] = sres;
    }
}

// ---------------------------------------------------------------------------
// Softmax; mask dtype sniffed inline from word 0 (uint8 / int32 / float32).
// ---------------------------------------------------------------------------
__global__ void softmax_kernel(const void* __restrict__ mask,
                               float* __restrict__ attn) {
    const int b   = blockIdx.x;
    const int tid = threadIdx.x;  // 256
    __shared__ float red[8];

    unsigned w0 = ((const unsigned int*)mask)[0];
    const int mode = (w0 == 0x01010101u) ? 0 : (w0 == 0x3F800000u) ? 2 : 1;

    float vals[8];
    float lmax = -1e30f;
    #pragma unroll
    for (int i = 0; i < 8; i++) {
        size_t f = (size_t)b * S_ + tid + i * 256;
        float sc = 0.f;
        #pragma unroll
        for (int x = 0; x < NTILES; x++) sc += g_part[(size_t)x * M_ + f];
        bool alive;
        if (mode == 0)      alive = ((const unsigned char*)mask)[f] != 0;
        else if (mode == 1) alive = ((const int*)mask)[f] != 0;
        else                alive = ((const float*)mask)[f] != 0.0f;
        if (!alive) sc = -1e9f;
        vals[i] = sc;
        lmax = fmaxf(lmax, sc);
    }
    float m = lmax;
    #pragma unroll
    for (int off = 16; off; off >>= 1)
        m = fmaxf(m, __shfl_xor_sync(0xffffffffu, m, off));
    if ((tid & 31) == 0) red[tid >> 5] = m;
    __syncthreads();
    float bm = red[0];
    #pragma unroll
    for (int i = 1; i < 8; i++) bm = fmaxf(bm, red[i]);

    float lsum = 0.f;
    #pragma unroll
    for (int i = 0; i < 8; i++) {
        vals[i] = expf(vals[i] - bm);
        lsum += vals[i];
    }
    #pragma unroll
    for (int off = 16; off; off >>= 1)
        lsum += __shfl_xor_sync(0xffffffffu, lsum, off);
    __syncthreads();
    if ((tid & 31) == 0) red[tid >> 5] = lsum;
    __syncthreads();
    float tot = 0.f;
    #pragma unroll
    for (int i = 0; i < 8; i++) tot += red[i];
    float inv = 1.f / tot;

    #pragma unroll
    for (int i = 0; i < 8; i++)
        attn[(size_t)b * S_ + tid + i * 256] = vals[i] * inv;
}

// ---------------------------------------------------------------------------
// context from fp16 enc copy (halved read traffic).
// ---------------------------------------------------------------------------
__global__ void context_kernel(const float* __restrict__ attn,
                               float* __restrict__ ctx) {
    const int b  = blockIdx.x;
    const int h  = blockIdx.y * 128 + (threadIdx.x & 127);
    const int sp = threadIdx.x >> 7;
    const __half* e = g_ench + (size_t)b * S_ * H_ + h;
    const float* w = attn + (size_t)b * S_;
    float acc = 0.f;
    #pragma unroll 8
    for (int s = sp; s < S_; s += 2)
        acc = fmaf(w[s], __half2float(e[(size_t)s * H_]), acc);
    __shared__ float sh[256];
    sh[threadIdx.x] = acc;
    __syncthreads();
    if (threadIdx.x < 128)
        ctx[(size_t)b * H_ + h] = sh[threadIdx.x] + sh[threadIdx.x + 128];
}

// ---------------------------------------------------------------------------
extern "C" void kernel_launch(void* const* d_in, const int* in_sizes, int n_in,
                              void* d_out, int out_size) {
    (void)in_sizes; (void)n_in; (void)out_size;
    const float* dec  = (const float*)d_in[0];
    const float* enc  = (const float*)d_in[1];
    const void*  mask = (const void*)d_in[2];
    const float* Wenc = (const float*)d_in[3];
    const float* Wdec = (const float*)d_in[4];
    const float* v    = (const float*)d_in[5];
    float* out  = (float*)d_out;
    float* attn = out + (size_t)B_ * H_;

    cudaFuncSetAttribute(fused_score_kernel,
                         cudaFuncAttributeMaxDynamicSharedMemorySize, DYN_BYTES);

    cvt_enc_kernel<<<65536, 256>>>(enc);
    cvt_w_kernel<<<512, 256>>>(Wenc);
    dec_proj_kernel<<<2048, 256>>>(dec, Wdec);
    dim3 g2(NTILES, M_ / MT);                 // (8, 512), x fastest -> L2 reuse
    fused_score_kernel<<<g2, 256, DYN_BYTES>>>(v);
    softmax_kernel<<<B_, 256>>>(mask, attn);
    context_kernel<<<dim3(B_, H_ / 128), 256>>>(attn, out);
}

// round 15
// speedup vs baseline: 1.0857x; 1.0290x over previous
#include <cuda_runtime.h>
#include <cuda_fp16.h>
#include <cstdint>
#include <math.h>

#define B_ 64
#define S_ 2048
#define H_ 1024
#define M_ (B_*S_)
#define NTILES 8          // H_/128 N-blocks
#define KT 64             // k elems per tile
#define K_ITERS (H_/KT)   // 16
#define RS 144            // smem row stride bytes (128B data + 16 pad)
#define MT 128            // CTA tile M
#define NT 128            // CTA tile N
#define ASTG (MT*RS)      // 18432
#define BSTG (NT*RS)      // 18432
#define STG  (ASTG+BSTG)  // 36864
#define NSTG 3
#define DYN_BYTES (NSTG*STG)   // 110592 -> 2 CTAs/SM

__device__ float  g_dp[B_ * H_];
__device__ float  g_part[NTILES * M_];
__device__ __half g_ench[(size_t)M_ * H_];   // 256 MB fp16 copy of enc
__device__ __half g_wh[(size_t)H_ * H_];     // 2 MB fp16 copy of W_enc

__device__ __forceinline__ uint32_t smem_u32(const void* p) {
    uint32_t a;
    asm("{ .reg .u64 t; cvta.to.shared.u64 t, %1; cvt.u32.u64 %0, t; }" : "=r"(a) : "l"(p));
    return a;
}
__device__ __forceinline__ void cp_async16(uint32_t dst, const void* src) {
    asm volatile("cp.async.cg.shared.global [%0], [%1], 16;" :: "r"(dst), "l"(src));
}
__device__ __forceinline__ void ldsm_x4(uint32_t r[4], uint32_t addr) {
    asm volatile("ldmatrix.sync.aligned.m8n8.x4.shared.b16 {%0,%1,%2,%3}, [%4];"
                 : "=r"(r[0]), "=r"(r[1]), "=r"(r[2]), "=r"(r[3]) : "r"(addr));
}
__device__ __forceinline__ void mma_f16(float c[4], const uint32_t a[4],
                                        uint32_t b0, uint32_t b1) {
    asm volatile(
        "mma.sync.aligned.m16n8k16.row.col.f32.f16.f16.f32 "
        "{%0,%1,%2,%3}, {%4,%5,%6,%7}, {%8,%9}, {%0,%1,%2,%3};"
        : "+f"(c[0]), "+f"(c[1]), "+f"(c[2]), "+f"(c[3])
        : "r"(a[0]), "r"(a[1]), "r"(a[2]), "r"(a[3]), "r"(b0), "r"(b1));
}
__device__ __forceinline__ float fast_tanh(float x) {
    float y; asm("tanh.approx.f32 %0, %1;" : "=f"(y) : "f"(x)); return y;
}

// ---------------------------------------------------------------------------
__global__ void cvt_enc_kernel(const float* __restrict__ src) {
    size_t c = (size_t)blockIdx.x * blockDim.x + threadIdx.x;
    const float4* s = (const float4*)src + c * 2;
    float4 a = s[0], b = s[1];
    __half2 h[4];
    h[0] = __floats2half2_rn(a.x, a.y);
    h[1] = __floats2half2_rn(a.z, a.w);
    h[2] = __floats2half2_rn(b.x, b.y);
    h[3] = __floats2half2_rn(b.z, b.w);
    *((uint4*)g_ench + c) = *(uint4*)h;
}
__global__ void cvt_w_kernel(const float* __restrict__ src) {
    size_t c = (size_t)blockIdx.x * blockDim.x + threadIdx.x;
    const float4* s = (const float4*)src + c * 2;
    float4 a = s[0], b = s[1];
    __half2 h[4];
    h[0] = __floats2half2_rn(a.x, a.y);
    h[1] = __floats2half2_rn(a.z, a.w);
    h[2] = __floats2half2_rn(b.x, b.y);
    h[3] = __floats2half2_rn(b.z, b.w);
    *((uint4*)g_wh + c) = *(uint4*)h;
}

// ---------------------------------------------------------------------------
__global__ void dec_proj_kernel(const float* __restrict__ dec,
                                const float* __restrict__ Wdec) {
    int wid  = (blockIdx.x * blockDim.x + threadIdx.x) >> 5;
    int lane = threadIdx.x & 31;
    int o  = wid >> 4;
    int b0 = (wid & 15) * 4;
    const float* wr = Wdec + (size_t)o * H_;
    const float* d0 = dec + (size_t)(b0 + 0) * H_;
    const float* d1 = dec + (size_t)(b0 + 1) * H_;
    const float* d2 = dec + (size_t)(b0 + 2) * H_;
    const float* d3 = dec + (size_t)(b0 + 3) * H_;
    float a0 = 0.f, a1 = 0.f, a2 = 0.f, a3 = 0.f;
    #pragma unroll 4
    for (int h = lane; h < H_; h += 32) {
        float w = wr[h];
        a0 = fmaf(w, d0[h], a0);
        a1 = fmaf(w, d1[h], a1);
        a2 = fmaf(w, d2[h], a2);
        a3 = fmaf(w, d3[h], a3);
    }
    #pragma unroll
    for (int off = 16; off; off >>= 1) {
        a0 += __shfl_down_sync(0xffffffffu, a0, off);
        a1 += __shfl_down_sync(0xffffffffu, a1, off);
        a2 += __shfl_down_sync(0xffffffffu, a2, off);
        a3 += __shfl_down_sync(0xffffffffu, a3, off);
    }
    if (lane == 0) {
        g_dp[(size_t)(b0 + 0) * H_ + o] = a0;
        g_dp[(size_t)(b0 + 1) * H_ + o] = a1;
        g_dp[(size_t)(b0 + 2) * H_ + o] = a2;
        g_dp[(size_t)(b0 + 3) * H_ + o] = a3;
    }
}

// ---------------------------------------------------------------------------
// Fused fp16 MMA GEMM (encH @ WencH^T) + tanh(.+dec_proj).v partial reduction.
// CTA tile 128(M)x128(N), 128 threads, 4 warps = 2(M)x2(N), warp tile 64x64.
// 2 CTAs/SM: two independent barrier domains interleave so per-ktile
// wait_group/__syncthreads bubbles of one CTA are covered by the other.
// cp.async 3-stage ring; f32 accumulators.
// ---------------------------------------------------------------------------
__global__ void __launch_bounds__(128, 2)
fused_score_kernel(const float* __restrict__ v) {
    extern __shared__ __align__(16) char dynsm[];
    __shared__ float dp_sh[NT];
    __shared__ float v_sh[NT];
    __shared__ float part_sh[2][MT];

    const int tid   = threadIdx.x;
    const int lane  = tid & 31;
    const int warp  = tid >> 5;     // 0..3
    const int warpM = warp & 1;     // 0..1
    const int warpN = warp >> 1;    // 0..1
    const int g = lane >> 2;
    const int t = lane & 3;

    const int nBase = blockIdx.x * NT;
    const int mBase = blockIdx.y * MT;
    const int b     = mBase >> 11;  // 128 | 2048 -> single batch per tile

    dp_sh[tid] = g_dp[(size_t)b * H_ + nBase + tid];
    v_sh[tid]  = v[nBase + tid];

    const uint32_t sm0 = smem_u32(dynsm);
    const __half* encH = g_ench;
    const __half* wH   = g_wh;

    float acc[4][8][4];
    #pragma unroll
    for (int mi = 0; mi < 4; mi++)
        #pragma unroll
        for (int ni = 0; ni < 8; ni++)
            #pragma unroll
            for (int c = 0; c < 4; c++) acc[mi][ni][c] = 0.f;

    // cp.async per ktile(64): A = 1024 chunks (16B), B = 1024; 128 threads.
#define ISSUE(J) {                                                          \
    const uint32_t sa_ = sm0 + ((J) % NSTG) * STG;                          \
    const uint32_t sb_ = sa_ + ASTG;                                        \
    const size_t ko_ = (size_t)(J) * KT;                                    \
    _Pragma("unroll")                                                       \
    for (int i_ = 0; i_ < 8; i_++) {                                        \
        int c_ = tid + (i_ << 7);                                           \
        int r_ = c_ >> 3, q_ = c_ & 7;                                      \
        cp_async16(sa_ + r_ * RS + q_ * 16,                                 \
                   encH + (size_t)(mBase + r_) * H_ + ko_ + q_ * 8);        \
    }                                                                       \
    _Pragma("unroll")                                                       \
    for (int i_ = 0; i_ < 8; i_++) {                                        \
        int c_ = tid + (i_ << 7);                                           \
        int r_ = c_ >> 3, q_ = c_ & 7;                                      \
        cp_async16(sb_ + r_ * RS + q_ * 16,                                 \
                   wH + (size_t)(nBase + r_) * H_ + ko_ + q_ * 8);          \
    } }

    // ldmatrix per-lane address components
    const int aRow = warpM * 64 + (lane & 7) + ((lane >> 3) & 1) * 8;
    const int aCol = ((lane >> 4) & 1) * 16;
    const int bRow = warpN * 64 + (lane >> 4) * 8 + (lane & 7);
    const int bCol = ((lane >> 3) & 1) * 16;

#define COMPUTE(BUF) {                                                     \
    const uint32_t Ab = sm0 + (BUF) * STG;                                  \
    const uint32_t Bb = Ab + ASTG;                                          \
    _Pragma("unroll")                                                       \
    for (int ks = 0; ks < 4; ks++) {                                        \
        uint32_t af[4][4], bf[4][4];                                        \
        _Pragma("unroll")                                                   \
        for (int mi = 0; mi < 4; mi++)                                      \
            ldsm_x4(af[mi], Ab + (aRow + mi * 16) * RS + ks * 32 + aCol);   \
        _Pragma("unroll")                                                   \
        for (int nj = 0; nj < 4; nj++)                                      \
            ldsm_x4(bf[nj], Bb + (bRow + nj * 16) * RS + ks * 32 + bCol);   \
        _Pragma("unroll")                                                   \
        for (int mi = 0; mi < 4; mi++) {                                    \
            _Pragma("unroll")                                               \
            for (int nj = 0; nj < 4; nj++) {                                \
                mma_f16(acc[mi][2*nj],   af[mi], bf[nj][0], bf[nj][1]);     \
                mma_f16(acc[mi][2*nj+1], af[mi], bf[nj][2], bf[nj][3]);     \
            }                                                               \
        }                                                                   \
    } }

    // prologue: 2 stages in flight
    ISSUE(0); asm volatile("cp.async.commit_group;");
    ISSUE(1); asm volatile("cp.async.commit_group;");

    #pragma unroll 1
    for (int kt = 0; kt < K_ITERS; kt++) {
        asm volatile("cp.async.wait_group 1;");
        __syncthreads();
        COMPUTE(kt % NSTG);
        if (kt + 2 < K_ITERS) ISSUE(kt + 2);
        asm volatile("cp.async.commit_group;");
    }
#undef ISSUE
#undef COMPUTE

    // Epilogue: energy = tanh(acc + dec_proj), partial = sum_col energy * v
    float rs[8];
    #pragma unroll
    for (int i = 0; i < 8; i++) rs[i] = 0.f;

    #pragma unroll
    for (int mi = 0; mi < 4; mi++) {
        #pragma unroll
        for (int ni = 0; ni < 8; ni++) {
            int c0 = warpN * 64 + ni * 8 + 2 * t;
            float d0 = dp_sh[c0],     d1 = dp_sh[c0 + 1];
            float w0 = v_sh[c0],      w1 = v_sh[c0 + 1];
            rs[2 * mi]     += fast_tanh(acc[mi][ni][0] + d0) * w0
                            + fast_tanh(acc[mi][ni][1] + d1) * w1;
            rs[2 * mi + 1] += fast_tanh(acc[mi][ni][2] + d0) * w0
                            + fast_tanh(acc[mi][ni][3] + d1) * w1;
        }
    }
    #pragma unroll
    for (int i = 0; i < 8; i++) {
        rs[i] += __shfl_xor_sync(0xffffffffu, rs[i], 1);
        rs[i] += __shfl_xor_sync(0xffffffffu, rs[i], 2);
    }
    if (t == 0) {
        #pragma unroll
        for (int mi = 0; mi < 4; mi++) {
            part_sh[warpN][warpM * 64 + mi * 16 + g]     = rs[2 * mi];
            part_sh[warpN][warpM * 64 + mi * 16 + g + 8] = rs[2 * mi + 1];
        }
    }
    __syncthreads();
    {
        float sres = part_sh[0][tid] + part_sh[1][tid];
        g_part[(size_t)blockIdx.x * M_ + mBase + tid] = sres;
    }
}

// ---------------------------------------------------------------------------
// Softmax; mask dtype sniffed inline from word 0 (uint8 / int32 / float32).
// ---------------------------------------------------------------------------
__global__ void softmax_kernel(const void* __restrict__ mask,
                               float* __restrict__ attn) {
    const int b   = blockIdx.x;
    const int tid = threadIdx.x;  // 256
    __shared__ float red[8];

    unsigned w0 = ((const unsigned int*)mask)[0];
    const int mode = (w0 == 0x01010101u) ? 0 : (w0 == 0x3F800000u) ? 2 : 1;

    float vals[8];
    float lmax = -1e30f;
    #pragma unroll
    for (int i = 0; i < 8; i++) {
        size_t f = (size_t)b * S_ + tid + i * 256;
        float sc = 0.f;
        #pragma unroll
        for (int x = 0; x < NTILES; x++) sc += g_part[(size_t)x * M_ + f];
        bool alive;
        if (mode == 0)      alive = ((const unsigned char*)mask)[f] != 0;
        else if (mode == 1) alive = ((const int*)mask)[f] != 0;
        else                alive = ((const float*)mask)[f] != 0.0f;
        if (!alive) sc = -1e9f;
        vals[i] = sc;
        lmax = fmaxf(lmax, sc);
    }
    float m = lmax;
    #pragma unroll
    for (int off = 16; off; off >>= 1)
        m = fmaxf(m, __shfl_xor_sync(0xffffffffu, m, off));
    if ((tid & 31) == 0) red[tid >> 5] = m;
    __syncthreads();
    float bm = red[0];
    #pragma unroll
    for (int i = 1; i < 8; i++) bm = fmaxf(bm, red[i]);

    float lsum = 0.f;
    #pragma unroll
    for (int i = 0; i < 8; i++) {
        vals[i] = expf(vals[i] - bm);
        lsum += vals[i];
    }
    #pragma unroll
    for (int off = 16; off; off >>= 1)
        lsum += __shfl_xor_sync(0xffffffffu, lsum, off);
    __syncthreads();
    if ((tid & 31) == 0) red[tid >> 5] = lsum;
    __syncthreads();
    float tot = 0.f;
    #pragma unroll
    for (int i = 0; i < 8; i++) tot += red[i];
    float inv = 1.f / tot;

    #pragma unroll
    for (int i = 0; i < 8; i++)
        attn[(size_t)b * S_ + tid + i * 256] = vals[i] * inv;
}

// ---------------------------------------------------------------------------
// context from fp16 enc copy (halved read traffic).
// ---------------------------------------------------------------------------
__global__ void context_kernel(const float* __restrict__ attn,
                               float* __restrict__ ctx) {
    const int b  = blockIdx.x;
    const int h  = blockIdx.y * 128 + (threadIdx.x & 127);
    const int sp = threadIdx.x >> 7;
    const __half* e = g_ench + (size_t)b * S_ * H_ + h;
    const float* w = attn + (size_t)b * S_;
    float acc = 0.f;
    #pragma unroll 8
    for (int s = sp; s < S_; s += 2)
        acc = fmaf(w[s], __half2float(e[(size_t)s * H_]), acc);
    __shared__ float sh[256];
    sh[threadIdx.x] = acc;
    __syncthreads();
    if (threadIdx.x < 128)
        ctx[(size_t)b * H_ + h] = sh[threadIdx.x] + sh[threadIdx.x + 128];
}

// ---------------------------------------------------------------------------
extern "C" void kernel_launch(void* const* d_in, const int* in_sizes, int n_in,
                              void* d_out, int out_size) {
    (void)in_sizes; (void)n_in; (void)out_size;
    const float* dec  = (const float*)d_in[0];
    const float* enc  = (const float*)d_in[1];
    const void*  mask = (const void*)d_in[2];
    const float* Wenc = (const float*)d_in[3];
    const float* Wdec = (const float*)d_in[4];
    const float* v    = (const float*)d_in[5];
    float* out  = (float*)d_out;
    float* attn = out + (size_t)B_ * H_;

    cudaFuncSetAttribute(fused_score_kernel,
                         cudaFuncAttributeMaxDynamicSharedMemorySize, DYN_BYTES);

    cvt_enc_kernel<<<65536, 256>>>(enc);
    cvt_w_kernel<<<512, 256>>>(Wenc);
    dec_proj_kernel<<<2048, 256>>>(dec, Wdec);
    dim3 g2(NTILES, M_ / MT);                 // (8, 1024), x fastest -> L2 reuse
    fused_score_kernel<<<g2, 128, DYN_BYTES>>>(v);
    softmax_kernel<<<B_, 256>>>(mask, attn);
    context_kernel<<<dim3(B_, H_ / 128), 256>>>(attn, out);
}

// round 16
// speedup vs baseline: 1.1263x; 1.0374x over previous
#include <cuda_runtime.h>
#include <cuda_fp16.h>
#include <cstdint>
#include <math.h>

#define B_ 64
#define S_ 2048
#define H_ 1024
#define M_ (B_*S_)
#define NTILES 8          // H_/128 N-blocks
#define KT 64             // k elems per tile
#define K_ITERS (H_/KT)   // 16
#define RS 144            // smem row stride bytes (128B data + 16 pad)
#define MT 128            // CTA tile M
#define NT 128            // CTA tile N
#define ASTG (MT*RS)      // 18432
#define BSTG (NT*RS)      // 18432
#define STG  (ASTG+BSTG)  // 36864
#define NSTG 3
#define DYN_BYTES (NSTG*STG)   // 110592 -> 2 CTAs/SM

__device__ float  g_dp[B_ * H_];
__device__ float  g_part[NTILES * M_];
__device__ __half g_ench[(size_t)M_ * H_];   // 256 MB fp16 copy of enc
__device__ __half g_wh[(size_t)H_ * H_];     // 2 MB fp16 copy of W_enc

__device__ __forceinline__ uint32_t smem_u32(const void* p) {
    uint32_t a;
    asm("{ .reg .u64 t; cvta.to.shared.u64 t, %1; cvt.u32.u64 %0, t; }" : "=r"(a) : "l"(p));
    return a;
}
__device__ __forceinline__ void cp_async16(uint32_t dst, const void* src) {
    asm volatile("cp.async.cg.shared.global [%0], [%1], 16;" :: "r"(dst), "l"(src));
}
__device__ __forceinline__ void ldsm_x4(uint32_t r[4], uint32_t addr) {
    asm volatile("ldmatrix.sync.aligned.m8n8.x4.shared.b16 {%0,%1,%2,%3}, [%4];"
                 : "=r"(r[0]), "=r"(r[1]), "=r"(r[2]), "=r"(r[3]) : "r"(addr));
}
__device__ __forceinline__ void mma_f16(float c[4], const uint32_t a[4],
                                        uint32_t b0, uint32_t b1) {
    asm volatile(
        "mma.sync.aligned.m16n8k16.row.col.f32.f16.f16.f32 "
        "{%0,%1,%2,%3}, {%4,%5,%6,%7}, {%8,%9}, {%0,%1,%2,%3};"
        : "+f"(c[0]), "+f"(c[1]), "+f"(c[2]), "+f"(c[3])
        : "r"(a[0]), "r"(a[1]), "r"(a[2]), "r"(a[3]), "r"(b0), "r"(b1));
}
__device__ __forceinline__ float fast_tanh(float x) {
    float y; asm("tanh.approx.f32 %0, %1;" : "=f"(y) : "f"(x)); return y;
}

// ---------------------------------------------------------------------------
__global__ void cvt_enc_kernel(const float* __restrict__ src) {
    size_t c = (size_t)blockIdx.x * blockDim.x + threadIdx.x;
    const float4* s = (const float4*)src + c * 2;
    float4 a = s[0], b = s[1];
    __half2 h[4];
    h[0] = __floats2half2_rn(a.x, a.y);
    h[1] = __floats2half2_rn(a.z, a.w);
    h[2] = __floats2half2_rn(b.x, b.y);
    h[3] = __floats2half2_rn(b.z, b.w);
    *((uint4*)g_ench + c) = *(uint4*)h;
}

// ---------------------------------------------------------------------------
// Merged prep: blocks [0,512) convert W_enc -> fp16; blocks [512,2560) compute
// dec_proj. One launch instead of two (fewer gaps).
// ---------------------------------------------------------------------------
__global__ void prep_kernel(const float* __restrict__ dec,
                            const float* __restrict__ Wdec,
                            const float* __restrict__ Wenc) {
    if (blockIdx.x < 512) {
        size_t c = (size_t)blockIdx.x * blockDim.x + threadIdx.x;
        const float4* s = (const float4*)Wenc + c * 2;
        float4 a = s[0], b = s[1];
        __half2 h[4];
        h[0] = __floats2half2_rn(a.x, a.y);
        h[1] = __floats2half2_rn(a.z, a.w);
        h[2] = __floats2half2_rn(b.x, b.y);
        h[3] = __floats2half2_rn(b.z, b.w);
        *((uint4*)g_wh + c) = *(uint4*)h;
        return;
    }
    int wid  = ((blockIdx.x - 512) * blockDim.x + threadIdx.x) >> 5;
    int lane = threadIdx.x & 31;
    int o  = wid >> 4;
    int b0 = (wid & 15) * 4;
    const float* wr = Wdec + (size_t)o * H_;
    const float* d0 = dec + (size_t)(b0 + 0) * H_;
    const float* d1 = dec + (size_t)(b0 + 1) * H_;
    const float* d2 = dec + (size_t)(b0 + 2) * H_;
    const float* d3 = dec + (size_t)(b0 + 3) * H_;
    float a0 = 0.f, a1 = 0.f, a2 = 0.f, a3 = 0.f;
    #pragma unroll 4
    for (int h = lane; h < H_; h += 32) {
        float w = wr[h];
        a0 = fmaf(w, d0[h], a0);
        a1 = fmaf(w, d1[h], a1);
        a2 = fmaf(w, d2[h], a2);
        a3 = fmaf(w, d3[h], a3);
    }
    #pragma unroll
    for (int off = 16; off; off >>= 1) {
        a0 += __shfl_down_sync(0xffffffffu, a0, off);
        a1 += __shfl_down_sync(0xffffffffu, a1, off);
        a2 += __shfl_down_sync(0xffffffffu, a2, off);
        a3 += __shfl_down_sync(0xffffffffu, a3, off);
    }
    if (lane == 0) {
        g_dp[(size_t)(b0 + 0) * H_ + o] = a0;
        g_dp[(size_t)(b0 + 1) * H_ + o] = a1;
        g_dp[(size_t)(b0 + 2) * H_ + o] = a2;
        g_dp[(size_t)(b0 + 3) * H_ + o] = a3;
    }
}

// ---------------------------------------------------------------------------
// Fused fp16 MMA GEMM (encH @ WencH^T) + tanh(.+dec_proj).v partial reduction.
// CTA tile 128(M)x128(N), 128 threads, 4 warps = 2(M)x2(N), warp tile 64x64.
// 2 CTAs/SM; cp.async 3-stage ring; f32 accumulators.
// ks-phase rotation: warp w starts its ks walk at (w&3) so ldsm bursts of
// co-resident warps de-align and cover each other's latency.
// ---------------------------------------------------------------------------
__global__ void __launch_bounds__(128, 2)
fused_score_kernel(const float* __restrict__ v) {
    extern __shared__ __align__(16) char dynsm[];
    __shared__ float dp_sh[NT];
    __shared__ float v_sh[NT];
    __shared__ float part_sh[2][MT];

    const int tid   = threadIdx.x;
    const int lane  = tid & 31;
    const int warp  = tid >> 5;     // 0..3
    const int warpM = warp & 1;     // 0..1
    const int warpN = warp >> 1;    // 0..1
    const int g = lane >> 2;
    const int t = lane & 3;

    const int nBase = blockIdx.x * NT;
    const int mBase = blockIdx.y * MT;
    const int b     = mBase >> 11;  // 128 | 2048 -> single batch per tile

    dp_sh[tid] = g_dp[(size_t)b * H_ + nBase + tid];
    v_sh[tid]  = v[nBase + tid];

    const uint32_t sm0 = smem_u32(dynsm);
    const __half* encH = g_ench;
    const __half* wH   = g_wh;

    float acc[4][8][4];
    #pragma unroll
    for (int mi = 0; mi < 4; mi++)
        #pragma unroll
        for (int ni = 0; ni < 8; ni++)
            #pragma unroll
            for (int c = 0; c < 4; c++) acc[mi][ni][c] = 0.f;

    // cp.async per ktile(64): A = 1024 chunks (16B), B = 1024; 128 threads.
#define ISSUE(J) {                                                          \
    const uint32_t sa_ = sm0 + ((J) % NSTG) * STG;                          \
    const uint32_t sb_ = sa_ + ASTG;                                        \
    const size_t ko_ = (size_t)(J) * KT;                                    \
    _Pragma("unroll")                                                       \
    for (int i_ = 0; i_ < 8; i_++) {                                        \
        int c_ = tid + (i_ << 7);                                           \
        int r_ = c_ >> 3, q_ = c_ & 7;                                      \
        cp_async16(sa_ + r_ * RS + q_ * 16,                                 \
                   encH + (size_t)(mBase + r_) * H_ + ko_ + q_ * 8);        \
    }                                                                       \
    _Pragma("unroll")                                                       \
    for (int i_ = 0; i_ < 8; i_++) {                                        \
        int c_ = tid + (i_ << 7);                                           \
        int r_ = c_ >> 3, q_ = c_ & 7;                                      \
        cp_async16(sb_ + r_ * RS + q_ * 16,                                 \
                   wH + (size_t)(nBase + r_) * H_ + ko_ + q_ * 8);          \
    } }

    // ldmatrix per-lane address components
    const int aRow = warpM * 64 + (lane & 7) + ((lane >> 3) & 1) * 8;
    const int aCol = ((lane >> 4) & 1) * 16;
    const int bRow = warpN * 64 + (lane >> 4) * 8 + (lane & 7);
    const int bCol = ((lane >> 3) & 1) * 16;

#define COMPUTE(BUF) {                                                     \
    const uint32_t Ab = sm0 + (BUF) * STG;                                  \
    const uint32_t Bb = Ab + ASTG;                                          \
    _Pragma("unroll")                                                       \
    for (int i = 0; i < 4; i++) {                                           \
        const int ks = (i + warp) & 3;   /* per-warp phase rotation */      \
        uint32_t af[4][4], bf[4][4];                                        \
        _Pragma("unroll")                                                   \
        for (int mi = 0; mi < 4; mi++)                                      \
            ldsm_x4(af[mi], Ab + (aRow + mi * 16) * RS + ks * 32 + aCol);   \
        _Pragma("unroll")                                                   \
        for (int nj = 0; nj < 4; nj++)                                      \
            ldsm_x4(bf[nj], Bb + (bRow + nj * 16) * RS + ks * 32 + bCol);   \
        _Pragma("unroll")                                                   \
        for (int mi = 0; mi < 4; mi++) {                                    \
            _Pragma("unroll")                                               \
            for (int nj = 0; nj < 4; nj++) {                                \
                mma_f16(acc[mi][2*nj],   af[mi], bf[nj][0], bf[nj][1]);     \
                mma_f16(acc[mi][2*nj+1], af[mi], bf[nj][2], bf[nj][3]);     \
            }                                                               \
        }                                                                   \
    } }

    // prologue: 2 stages in flight
    ISSUE(0); asm volatile("cp.async.commit_group;");
    ISSUE(1); asm volatile("cp.async.commit_group;");

    #pragma unroll 1
    for (int kt = 0; kt < K_ITERS; kt++) {
        asm volatile("cp.async.wait_group 1;");
        __syncthreads();
        if (kt + 2 < K_ITERS) ISSUE(kt + 2);   // issue early: in flight under COMPUTE
        asm volatile("cp.async.commit_group;");
        COMPUTE(kt % NSTG);
    }
#undef ISSUE
#undef COMPUTE

    // Epilogue: energy = tanh(acc + dec_proj), partial = sum_col energy * v
    float rs[8];
    #pragma unroll
    for (int i = 0; i < 8; i++) rs[i] = 0.f;

    #pragma unroll
    for (int mi = 0; mi < 4; mi++) {
        #pragma unroll
        for (int ni = 0; ni < 8; ni++) {
            int c0 = warpN * 64 + ni * 8 + 2 * t;
            float d0 = dp_sh[c0],     d1 = dp_sh[c0 + 1];
            float w0 = v_sh[c0],      w1 = v_sh[c0 + 1];
            rs[2 * mi]     += fast_tanh(acc[mi][ni][0] + d0) * w0
                            + fast_tanh(acc[mi][ni][1] + d1) * w1;
            rs[2 * mi + 1] += fast_tanh(acc[mi][ni][2] + d0) * w0
                            + fast_tanh(acc[mi][ni][3] + d1) * w1;
        }
    }
    #pragma unroll
    for (int i = 0; i < 8; i++) {
        rs[i] += __shfl_xor_sync(0xffffffffu, rs[i], 1);
        rs[i] += __shfl_xor_sync(0xffffffffu, rs[i], 2);
    }
    if (t == 0) {
        #pragma unroll
        for (int mi = 0; mi < 4; mi++) {
            part_sh[warpN][warpM * 64 + mi * 16 + g]     = rs[2 * mi];
            part_sh[warpN][warpM * 64 + mi * 16 + g + 8] = rs[2 * mi + 1];
        }
    }
    __syncthreads();
    {
        float sres = part_sh[0][tid] + part_sh[1][tid];
        g_part[(size_t)blockIdx.x * M_ + mBase + tid] = sres;
    }
}

// ---------------------------------------------------------------------------
// Softmax; mask dtype sniffed inline from word 0 (uint8 / int32 / float32).
// ---------------------------------------------------------------------------
__global__ void softmax_kernel(const void* __restrict__ mask,
                               float* __restrict__ attn) {
    const int b   = blockIdx.x;
    const int tid = threadIdx.x;  // 256
    __shared__ float red[8];

    unsigned w0 = ((const unsigned int*)mask)[0];
    const int mode = (w0 == 0x01010101u) ? 0 : (w0 == 0x3F800000u) ? 2 : 1;

    float vals[8];
    float lmax = -1e30f;
    #pragma unroll
    for (int i = 0; i < 8; i++) {
        size_t f = (size_t)b * S_ + tid + i * 256;
        float sc = 0.f;
        #pragma unroll
        for (int x = 0; x < NTILES; x++) sc += g_part[(size_t)x * M_ + f];
        bool alive;
        if (mode == 0)      alive = ((const unsigned char*)mask)[f] != 0;
        else if (mode == 1) alive = ((const int*)mask)[f] != 0;
        else                alive = ((const float*)mask)[f] != 0.0f;
        if (!alive) sc = -1e9f;
        vals[i] = sc;
        lmax = fmaxf(lmax, sc);
    }
    float m = lmax;
    #pragma unroll
    for (int off = 16; off; off >>= 1)
        m = fmaxf(m, __shfl_xor_sync(0xffffffffu, m, off));
    if ((tid & 31) == 0) red[tid >> 5] = m;
    __syncthreads();
    float bm = red[0];
    #pragma unroll
    for (int i = 1; i < 8; i++) bm = fmaxf(bm, red[i]);

    float lsum = 0.f;
    #pragma unroll
    for (int i = 0; i < 8; i++) {
        vals[i] = expf(vals[i] - bm);
        lsum += vals[i];
    }
    #pragma unroll
    for (int off = 16; off; off >>= 1)
        lsum += __shfl_xor_sync(0xffffffffu, lsum, off);
    __syncthreads();
    if ((tid & 31) == 0) red[tid >> 5] = lsum;
    __syncthreads();
    float tot = 0.f;
    #pragma unroll
    for (int i = 0; i < 8; i++) tot += red[i];
    float inv = 1.f / tot;

    #pragma unroll
    for (int i = 0; i < 8; i++)
        attn[(size_t)b * S_ + tid + i * 256] = vals[i] * inv;
}

// ---------------------------------------------------------------------------
// context from fp16 enc copy, vectorized: each thread loads uint4 = 8 halves.
// Block: one b, 128 h-cols; 256 threads = 16 h8-groups x 16 s-lanes.
// ---------------------------------------------------------------------------
__global__ void context_kernel(const float* __restrict__ attn,
                               float* __restrict__ ctx) {
    __shared__ float sh[16][16][8];   // [sp][h8][8]
    const int b   = blockIdx.x;
    const int tid = threadIdx.x;      // 256
    const int h8  = tid & 15;         // h-group (8 halves each)
    const int sp  = tid >> 4;         // s-lane 0..15
    const int hBase = blockIdx.y * 128 + h8 * 8;

    const __half* e = g_ench + (size_t)b * S_ * H_ + hBase;
    const float*  w = attn + (size_t)b * S_;

    float acc[8];
    #pragma unroll
    for (int i = 0; i < 8; i++) acc[i] = 0.f;

    #pragma unroll 4
    for (int s = sp; s < S_; s += 16) {
        uint4 u = *(const uint4*)(e + (size_t)s * H_);
        float ws = w[s];
        const __half2* hp = (const __half2*)&u;
        #pragma unroll
        for (int j = 0; j < 4; j++) {
            float2 f = __half22float2(hp[j]);
            acc[2*j]     = fmaf(ws, f.x, acc[2*j]);
            acc[2*j + 1] = fmaf(ws, f.y, acc[2*j + 1]);
        }
    }
    #pragma unroll
    for (int i = 0; i < 8; i++) sh[sp][h8][i] = acc[i];
    __syncthreads();

    #pragma unroll
    for (int stride = 8; stride; stride >>= 1) {
        if (sp < stride) {
            #pragma unroll
            for (int i = 0; i < 8; i++)
                sh[sp][h8][i] += sh[sp + stride][h8][i];
        }
        __syncthreads();
    }
    if (sp == 0) {
        float* o = ctx + (size_t)b * H_ + hBase;
        #pragma unroll
        for (int i = 0; i < 8; i++) o[i] = sh[0][h8][i];
    }
}

// ---------------------------------------------------------------------------
extern "C" void kernel_launch(void* const* d_in, const int* in_sizes, int n_in,
                              void* d_out, int out_size) {
    (void)in_sizes; (void)n_in; (void)out_size;
    const float* dec  = (const float*)d_in[0];
    const float* enc  = (const float*)d_in[1];
    const void*  mask = (const void*)d_in[2];
    const float* Wenc = (const float*)d_in[3];
    const float* Wdec = (const float*)d_in[4];
    const float* v    = (const float*)d_in[5];
    float* out  = (float*)d_out;
    float* attn = out + (size_t)B_ * H_;

    cudaFuncSetAttribute(fused_score_kernel,
                         cudaFuncAttributeMaxDynamicSharedMemorySize, DYN_BYTES);

    cvt_enc_kernel<<<65536, 256>>>(enc);
    prep_kernel<<<2560, 256>>>(dec, Wdec, Wenc);   // cvt_w + dec_proj merged
    dim3 g2(NTILES, M_ / MT);                 // (8, 1024), x fastest -> L2 reuse
    fused_score_kernel<<<g2, 128, DYN_BYTES>>>(v);
    softmax_kernel<<<B_, 256>>>(mask, attn);
    context_kernel<<<dim3(B_, H_ / 128), 256>>>(attn, out);
}

// round 17
// speedup vs baseline: 1.1290x; 1.0024x over previous
#include <cuda_runtime.h>
#include <cuda_fp16.h>
#include <cstdint>
#include <math.h>

#define B_ 64
#define S_ 2048
#define H_ 1024
#define M_ (B_*S_)
#define NTILES 8          // H_/128 N-blocks
#define KT 64             // k elems per tile
#define K_ITERS (H_/KT)   // 16
#define RS 144            // smem row stride bytes (128B data + 16 pad)
#define MT 128            // CTA tile M
#define NT 128            // CTA tile N
#define ASTG (MT*RS)      // 18432
#define BSTG (NT*RS)      // 18432
#define STG  (ASTG+BSTG)  // 36864
#define NSTG 3
#define DYN_BYTES (NSTG*STG)   // 110592 -> 2 CTAs/SM

__device__ float  g_dp[B_ * H_];
__device__ float  g_part[NTILES * M_];
__device__ __half g_ench[(size_t)M_ * H_];   // 256 MB fp16 copy of enc
__device__ __half g_wh[(size_t)H_ * H_];     // 2 MB fp16 copy of W_enc

__device__ __forceinline__ uint32_t smem_u32(const void* p) {
    uint32_t a;
    asm("{ .reg .u64 t; cvta.to.shared.u64 t, %1; cvt.u32.u64 %0, t; }" : "=r"(a) : "l"(p));
    return a;
}
__device__ __forceinline__ void cp_async16(uint32_t dst, const void* src) {
    asm volatile("cp.async.cg.shared.global [%0], [%1], 16;" :: "r"(dst), "l"(src));
}
__device__ __forceinline__ void ldsm_x4(uint32_t r[4], uint32_t addr) {
    asm volatile("ldmatrix.sync.aligned.m8n8.x4.shared.b16 {%0,%1,%2,%3}, [%4];"
                 : "=r"(r[0]), "=r"(r[1]), "=r"(r[2]), "=r"(r[3]) : "r"(addr));
}
__device__ __forceinline__ void mma_f16(float c[4], const uint32_t a[4],
                                        uint32_t b0, uint32_t b1) {
    asm volatile(
        "mma.sync.aligned.m16n8k16.row.col.f32.f16.f16.f32 "
        "{%0,%1,%2,%3}, {%4,%5,%6,%7}, {%8,%9}, {%0,%1,%2,%3};"
        : "+f"(c[0]), "+f"(c[1]), "+f"(c[2]), "+f"(c[3])
        : "r"(a[0]), "r"(a[1]), "r"(a[2]), "r"(a[3]), "r"(b0), "r"(b1));
}
__device__ __forceinline__ float fast_tanh(float x) {
    float y; asm("tanh.approx.f32 %0, %1;" : "=f"(y) : "f"(x)); return y;
}

// ---------------------------------------------------------------------------
// fp32 -> fp16 enc conversion, 16 floats per thread (MLP=4 independent LDG.128)
// grid 32768 x 256: 8.39M threads x 16 = 134.2M elements.
// ---------------------------------------------------------------------------
__global__ void cvt_enc_kernel(const float* __restrict__ src) {
    size_t c = (size_t)blockIdx.x * blockDim.x + threadIdx.x;
    const float4* s = (const float4*)src + c * 4;
    float4 a0 = s[0], a1 = s[1], a2 = s[2], a3 = s[3];
    uint4 o0, o1;
    __half2* p0 = (__half2*)&o0;
    __half2* p1 = (__half2*)&o1;
    p0[0] = __floats2half2_rn(a0.x, a0.y);
    p0[1] = __floats2half2_rn(a0.z, a0.w);
    p0[2] = __floats2half2_rn(a1.x, a1.y);
    p0[3] = __floats2half2_rn(a1.z, a1.w);
    p1[0] = __floats2half2_rn(a2.x, a2.y);
    p1[1] = __floats2half2_rn(a2.z, a2.w);
    p1[2] = __floats2half2_rn(a3.x, a3.y);
    p1[3] = __floats2half2_rn(a3.z, a3.w);
    uint4* d = (uint4*)g_ench + c * 2;
    d[0] = o0;
    d[1] = o1;
}

// ---------------------------------------------------------------------------
__global__ void cvt_w_kernel(const float* __restrict__ src) {
    size_t c = (size_t)blockIdx.x * blockDim.x + threadIdx.x;
    const float4* s = (const float4*)src + c * 2;
    float4 a = s[0], b = s[1];
    __half2 h[4];
    h[0] = __floats2half2_rn(a.x, a.y);
    h[1] = __floats2half2_rn(a.z, a.w);
    h[2] = __floats2half2_rn(b.x, b.y);
    h[3] = __floats2half2_rn(b.z, b.w);
    *((uint4*)g_wh + c) = *(uint4*)h;
}

// ---------------------------------------------------------------------------
// dec_proj with float4 loads (5 x LDG.128 per iter, 8 iters).
// ---------------------------------------------------------------------------
__global__ void dec_proj_kernel(const float* __restrict__ dec,
                                const float* __restrict__ Wdec) {
    int wid  = (blockIdx.x * blockDim.x + threadIdx.x) >> 5;
    int lane = threadIdx.x & 31;
    int o  = wid >> 4;
    int b0 = (wid & 15) * 4;
    const float4* wr = (const float4*)(Wdec + (size_t)o * H_);
    const float4* d0 = (const float4*)(dec + (size_t)(b0 + 0) * H_);
    const float4* d1 = (const float4*)(dec + (size_t)(b0 + 1) * H_);
    const float4* d2 = (const float4*)(dec + (size_t)(b0 + 2) * H_);
    const float4* d3 = (const float4*)(dec + (size_t)(b0 + 3) * H_);
    float a0 = 0.f, a1 = 0.f, a2 = 0.f, a3 = 0.f;
    #pragma unroll 4
    for (int h4 = lane; h4 < H_ / 4; h4 += 32) {
        float4 w = wr[h4];
        float4 x0 = d0[h4], x1 = d1[h4], x2 = d2[h4], x3 = d3[h4];
        a0 += w.x * x0.x + w.y * x0.y + w.z * x0.z + w.w * x0.w;
        a1 += w.x * x1.x + w.y * x1.y + w.z * x1.z + w.w * x1.w;
        a2 += w.x * x2.x + w.y * x2.y + w.z * x2.z + w.w * x2.w;
        a3 += w.x * x3.x + w.y * x3.y + w.z * x3.z + w.w * x3.w;
    }
    #pragma unroll
    for (int off = 16; off; off >>= 1) {
        a0 += __shfl_down_sync(0xffffffffu, a0, off);
        a1 += __shfl_down_sync(0xffffffffu, a1, off);
        a2 += __shfl_down_sync(0xffffffffu, a2, off);
        a3 += __shfl_down_sync(0xffffffffu, a3, off);
    }
    if (lane == 0) {
        g_dp[(size_t)(b0 + 0) * H_ + o] = a0;
        g_dp[(size_t)(b0 + 1) * H_ + o] = a1;
        g_dp[(size_t)(b0 + 2) * H_ + o] = a2;
        g_dp[(size_t)(b0 + 3) * H_ + o] = a3;
    }
}

// ---------------------------------------------------------------------------
// Fused fp16 MMA GEMM (encH @ WencH^T) + tanh(.+dec_proj).v partial reduction.
// CTA tile 128(M)x128(N), 128 threads, 4 warps = 2(M)x2(N), warp tile 64x64.
// 2 CTAs/SM; cp.async 3-stage ring; f32 accumulators; ks-phase rotation.
// (unchanged from round 16 -- profiled this round as launch #4)
// ---------------------------------------------------------------------------
__global__ void __launch_bounds__(128, 2)
fused_score_kernel(const float* __restrict__ v) {
    extern __shared__ __align__(16) char dynsm[];
    __shared__ float dp_sh[NT];
    __shared__ float v_sh[NT];
    __shared__ float part_sh[2][MT];

    const int tid   = threadIdx.x;
    const int lane  = tid & 31;
    const int warp  = tid >> 5;     // 0..3
    const int warpM = warp & 1;     // 0..1
    const int warpN = warp >> 1;    // 0..1
    const int g = lane >> 2;
    const int t = lane & 3;

    const int nBase = blockIdx.x * NT;
    const int mBase = blockIdx.y * MT;
    const int b     = mBase >> 11;  // 128 | 2048 -> single batch per tile

    dp_sh[tid] = g_dp[(size_t)b * H_ + nBase + tid];
    v_sh[tid]  = v[nBase + tid];

    const uint32_t sm0 = smem_u32(dynsm);
    const __half* encH = g_ench;
    const __half* wH   = g_wh;

    float acc[4][8][4];
    #pragma unroll
    for (int mi = 0; mi < 4; mi++)
        #pragma unroll
        for (int ni = 0; ni < 8; ni++)
            #pragma unroll
            for (int c = 0; c < 4; c++) acc[mi][ni][c] = 0.f;

    // cp.async per ktile(64): A = 1024 chunks (16B), B = 1024; 128 threads.
#define ISSUE(J) {                                                          \
    const uint32_t sa_ = sm0 + ((J) % NSTG) * STG;                          \
    const uint32_t sb_ = sa_ + ASTG;                                        \
    const size_t ko_ = (size_t)(J) * KT;                                    \
    _Pragma("unroll")                                                       \
    for (int i_ = 0; i_ < 8; i_++) {                                        \
        int c_ = tid + (i_ << 7);                                           \
        int r_ = c_ >> 3, q_ = c_ & 7;                                      \
        cp_async16(sa_ + r_ * RS + q_ * 16,                                 \
                   encH + (size_t)(mBase + r_) * H_ + ko_ + q_ * 8);        \
    }                                                                       \
    _Pragma("unroll")                                                       \
    for (int i_ = 0; i_ < 8; i_++) {                                        \
        int c_ = tid + (i_ << 7);                                           \
        int r_ = c_ >> 3, q_ = c_ & 7;                                      \
        cp_async16(sb_ + r_ * RS + q_ * 16,                                 \
                   wH + (size_t)(nBase + r_) * H_ + ko_ + q_ * 8);          \
    } }

    // ldmatrix per-lane address components
    const int aRow = warpM * 64 + (lane & 7) + ((lane >> 3) & 1) * 8;
    const int aCol = ((lane >> 4) & 1) * 16;
    const int bRow = warpN * 64 + (lane >> 4) * 8 + (lane & 7);
    const int bCol = ((lane >> 3) & 1) * 16;

#define COMPUTE(BUF) {                                                     \
    const uint32_t Ab = sm0 + (BUF) * STG;                                  \
    const uint32_t Bb = Ab + ASTG;                                          \
    _Pragma("unroll")                                                       \
    for (int i = 0; i < 4; i++) {                                           \
        const int ks = (i + warp) & 3;   /* per-warp phase rotation */      \
        uint32_t af[4][4], bf[4][4];                                        \
        _Pragma("unroll")                                                   \
        for (int mi = 0; mi < 4; mi++)                                      \
            ldsm_x4(af[mi], Ab + (aRow + mi * 16) * RS + ks * 32 + aCol);   \
        _Pragma("unroll")                                                   \
        for (int nj = 0; nj < 4; nj++)                                      \
            ldsm_x4(bf[nj], Bb + (bRow + nj * 16) * RS + ks * 32 + bCol);   \
        _Pragma("unroll")                                                   \
        for (int mi = 0; mi < 4; mi++) {                                    \
            _Pragma("unroll")                                               \
            for (int nj = 0; nj < 4; nj++) {                                \
                mma_f16(acc[mi][2*nj],   af[mi], bf[nj][0], bf[nj][1]);     \
                mma_f16(acc[mi][2*nj+1], af[mi], bf[nj][2], bf[nj][3]);     \
            }                                                               \
        }                                                                   \
    } }

    // prologue: 2 stages in flight
    ISSUE(0); asm volatile("cp.async.commit_group;");
    ISSUE(1); asm volatile("cp.async.commit_group;");

    #pragma unroll 1
    for (int kt = 0; kt < K_ITERS; kt++) {
        asm volatile("cp.async.wait_group 1;");
        __syncthreads();
        if (kt + 2 < K_ITERS) ISSUE(kt + 2);   // in flight under COMPUTE
        asm volatile("cp.async.commit_group;");
        COMPUTE(kt % NSTG);
    }
#undef ISSUE
#undef COMPUTE

    // Epilogue: energy = tanh(acc + dec_proj), partial = sum_col energy * v
    float rs[8];
    #pragma unroll
    for (int i = 0; i < 8; i++) rs[i] = 0.f;

    #pragma unroll
    for (int mi = 0; mi < 4; mi++) {
        #pragma unroll
        for (int ni = 0; ni < 8; ni++) {
            int c0 = warpN * 64 + ni * 8 + 2 * t;
            float d0 = dp_sh[c0],     d1 = dp_sh[c0 + 1];
            float w0 = v_sh[c0],      w1 = v_sh[c0 + 1];
            rs[2 * mi]     += fast_tanh(acc[mi][ni][0] + d0) * w0
                            + fast_tanh(acc[mi][ni][1] + d1) * w1;
            rs[2 * mi + 1] += fast_tanh(acc[mi][ni][2] + d0) * w0
                            + fast_tanh(acc[mi][ni][3] + d1) * w1;
        }
    }
    #pragma unroll
    for (int i = 0; i < 8; i++) {
        rs[i] += __shfl_xor_sync(0xffffffffu, rs[i], 1);
        rs[i] += __shfl_xor_sync(0xffffffffu, rs[i], 2);
    }
    if (t == 0) {
        #pragma unroll
        for (int mi = 0; mi < 4; mi++) {
            part_sh[warpN][warpM * 64 + mi * 16 + g]     = rs[2 * mi];
            part_sh[warpN][warpM * 64 + mi * 16 + g + 8] = rs[2 * mi + 1];
        }
    }
    __syncthreads();
    {
        float sres = part_sh[0][tid] + part_sh[1][tid];
        g_part[(size_t)blockIdx.x * M_ + mBase + tid] = sres;
    }
}

// ---------------------------------------------------------------------------
// Softmax; mask dtype sniffed inline from word 0 (uint8 / int32 / float32).
// ---------------------------------------------------------------------------
__global__ void softmax_kernel(const void* __restrict__ mask,
                               float* __restrict__ attn) {
    const int b   = blockIdx.x;
    const int tid = threadIdx.x;  // 256
    __shared__ float red[8];

    unsigned w0 = ((const unsigned int*)mask)[0];
    const int mode = (w0 == 0x01010101u) ? 0 : (w0 == 0x3F800000u) ? 2 : 1;

    float vals[8];
    float lmax = -1e30f;
    #pragma unroll
    for (int i = 0; i < 8; i++) {
        size_t f = (size_t)b * S_ + tid + i * 256;
        float sc = 0.f;
        #pragma unroll
        for (int x = 0; x < NTILES; x++) sc += g_part[(size_t)x * M_ + f];
        bool alive;
        if (mode == 0)      alive = ((const unsigned char*)mask)[f] != 0;
        else if (mode == 1) alive = ((const int*)mask)[f] != 0;
        else                alive = ((const float*)mask)[f] != 0.0f;
        if (!alive) sc = -1e9f;
        vals[i] = sc;
        lmax = fmaxf(lmax, sc);
    }
    float m = lmax;
    #pragma unroll
    for (int off = 16; off; off >>= 1)
        m = fmaxf(m, __shfl_xor_sync(0xffffffffu, m, off));
    if ((tid & 31) == 0) red[tid >> 5] = m;
    __syncthreads();
    float bm = red[0];
    #pragma unroll
    for (int i = 1; i < 8; i++) bm = fmaxf(bm, red[i]);

    float lsum = 0.f;
    #pragma unroll
    for (int i = 0; i < 8; i++) {
        vals[i] = expf(vals[i] - bm);
        lsum += vals[i];
    }
    #pragma unroll
    for (int off = 16; off; off >>= 1)
        lsum += __shfl_xor_sync(0xffffffffu, lsum, off);
    __syncthreads();
    if ((tid & 31) == 0) red[tid >> 5] = lsum;
    __syncthreads();
    float tot = 0.f;
    #pragma unroll
    for (int i = 0; i < 8; i++) tot += red[i];
    float inv = 1.f / tot;

    #pragma unroll
    for (int i = 0; i < 8; i++)
        attn[(size_t)b * S_ + tid + i * 256] = vals[i] * inv;
}

// ---------------------------------------------------------------------------
// context from fp16 enc copy, vectorized: each thread loads uint4 = 8 halves.
// ---------------------------------------------------------------------------
__global__ void context_kernel(const float* __restrict__ attn,
                               float* __restrict__ ctx) {
    __shared__ float sh[16][16][8];   // [sp][h8][8]
    const int b   = blockIdx.x;
    const int tid = threadIdx.x;      // 256
    const int h8  = tid & 15;         // h-group (8 halves each)
    const int sp  = tid >> 4;         // s-lane 0..15
    const int hBase = blockIdx.y * 128 + h8 * 8;

    const __half* e = g_ench + (size_t)b * S_ * H_ + hBase;
    const float*  w = attn + (size_t)b * S_;

    float acc[8];
    #pragma unroll
    for (int i = 0; i < 8; i++) acc[i] = 0.f;

    #pragma unroll 4
    for (int s = sp; s < S_; s += 16) {
        uint4 u = *(const uint4*)(e + (size_t)s * H_);
        float ws = w[s];
        const __half2* hp = (const __half2*)&u;
        #pragma unroll
        for (int j = 0; j < 4; j++) {
            float2 f = __half22float2(hp[j]);
            acc[2*j]     = fmaf(ws, f.x, acc[2*j]);
            acc[2*j + 1] = fmaf(ws, f.y, acc[2*j + 1]);
        }
    }
    #pragma unroll
    for (int i = 0; i < 8; i++) sh[sp][h8][i] = acc[i];
    __syncthreads();

    #pragma unroll
    for (int stride = 8; stride; stride >>= 1) {
        if (sp < stride) {
            #pragma unroll
            for (int i = 0; i < 8; i++)
                sh[sp][h8][i] += sh[sp + stride][h8][i];
        }
        __syncthreads();
    }
    if (sp == 0) {
        float* o = ctx + (size_t)b * H_ + hBase;
        #pragma unroll
        for (int i = 0; i < 8; i++) o[i] = sh[0][h8][i];
    }
}

// ---------------------------------------------------------------------------
extern "C" void kernel_launch(void* const* d_in, const int* in_sizes, int n_in,
                              void* d_out, int out_size) {
    (void)in_sizes; (void)n_in; (void)out_size;
    const float* dec  = (const float*)d_in[0];
    const float* enc  = (const float*)d_in[1];
    const void*  mask = (const void*)d_in[2];
    const float* Wenc = (const float*)d_in[3];
    const float* Wdec = (const float*)d_in[4];
    const float* v    = (const float*)d_in[5];
    float* out  = (float*)d_out;
    float* attn = out + (size_t)B_ * H_;

    cudaFuncSetAttribute(fused_score_kernel,
                         cudaFuncAttributeMaxDynamicSharedMemorySize, DYN_BYTES);

    cvt_enc_kernel<<<32768, 256>>>(enc);        // 1: 16 floats/thread, MLP=4
    cvt_w_kernel<<<512, 256>>>(Wenc);           // 2
    dec_proj_kernel<<<2048, 256>>>(dec, Wdec);  // 3
    dim3 g2(NTILES, M_ / MT);                   // (8, 1024), x fastest
    fused_score_kernel<<<g2, 128, DYN_BYTES>>>(v);   // 4 <- profiled
    softmax_kernel<<<B_, 256>>>(mask, attn);    // 5
    context_kernel<<<dim3(B_, H_ / 128), 256>>>(attn, out);  // 6
}